// round 10
// baseline (speedup 1.0000x reference)
#include <cuda_runtime.h>

// MovingNCA, plane-reduced formulation:
//  state(96ch) -> 9 planes P_ij = <state, comms_w[i,j,:]>.
//  comms a = b_c + sum_ij P_ij(n+i,m+j); percep b = 3x3 img gather at perc pos.
//  s_c = sigmoid(a*u_c + b*v_c + ob_c); planes += W^T s; class ch -> scratch.
// R10: identical to R9 except __launch_bounds__(256,3) -> 84-reg budget.
//      R9 sat exactly at the 64-reg cap and the issue-count evidence
//      (~2x static instruction count, L1 30%, alu 12%) indicates spills;
//      this buys the registers back at occ 25% (gains saturated at ~37%).

#define N_NEO 510
#define G     512
#define G2    (G * G)
#define NCELLS (N_NEO * N_NEO)
#define NCA_THRESH 0.0007f
#define NLOG2E (-1.4426950408889634f)

__device__ float   g_h[2][9][G2];        // ping-pong comms planes
__device__ float4  g_cls4[8][NCELLS];    // class accumulators, 4 ch per float4
__device__ ushort2 g_perc[NCELLS];       // perception positions

__global__ void nca_init() {
    long stride = (long)gridDim.x * blockDim.x;
    long tid = (long)blockIdx.x * blockDim.x + threadIdx.x;
    float* h = &g_h[0][0][0];
    for (long i = tid; i < 2L * 9 * G2; i += stride) h[i] = 0.0f;
    float* c = &g_cls4[0][0].x;
    for (long i = tid; i < 32L * NCELLS; i += stride) c[i] = 0.0f;
    for (long i = tid; i < NCELLS; i += stride)
        g_perc[i] = make_ushort2((unsigned short)(i / N_NEO),
                                 (unsigned short)(i % N_NEO));
}

__global__ void nca_final(float* __restrict__ out) {
    int cell = blockIdx.x * 256 + threadIdx.x;
    if (cell >= NCELLS) return;
    float* op = out + (size_t)cell * 32;
#pragma unroll
    for (int j = 0; j < 8; j++)
        *reinterpret_cast<float4*>(op + 4 * j) = g_cls4[j][cell];
}

// weights prescaled by -log2(e): computes sigmoid(z) from x = -log2(e)*z
__device__ __forceinline__ float sigmoid_pre(float x) {
    float e;
    asm("ex2.approx.f32 %0, %1;" : "=f"(e) : "f"(x));
    float r;
    asm("rcp.approx.f32 %0, %1;" : "=f"(r) : "f"(1.0f + e));
    return r;
}

__global__ __launch_bounds__(256, 3) void nca_step(
    const float* __restrict__ img,
    const float* __restrict__ comms_w,
    const float* __restrict__ comms_b,
    const float* __restrict__ perc_w,
    const float* __restrict__ perc_b,
    const float* __restrict__ out_w,
    const float* __restrict__ out_b,
    int parity)
{
    __shared__ __align__(16) float scw[9 * 96];   // comms_w [ij][c]
    __shared__ __align__(16) float su[100], sv[100], sob[100];  // prescaled
    __shared__ float spw[9];
    __shared__ float sbias[2];                    // [0]=perc_b [1]=comms_b

    int t = threadIdx.y * 32 + threadIdx.x;
    for (int i = t; i < 864; i += 256) scw[i] = comms_w[i];
    if (t < 98) {
        su[t]  = NLOG2E * out_w[t];
        sv[t]  = NLOG2E * out_w[98 + t];
        sob[t] = NLOG2E * out_b[t];
    }
    else if (t < 107) spw[t - 98] = perc_w[t - 98];
    else if (t == 107) sbias[0] = perc_b[0];
    else if (t == 108) sbias[1] = comms_b[0];
    __syncthreads();

    int n = blockIdx.y * 8 + threadIdx.y;
    if (n >= N_NEO) return;
    int m0 = blockIdx.x * 64 + threadIdx.x;

    const float* __restrict__ hOld = &g_h[parity][0][0];
    float* __restrict__ hNew = &g_h[parity ^ 1][0][0];

    bool valid[2];
    int  cellc[2];            // clamped cell index (safe reads)
    float a[2], b[2];
    ushort2 pp[2];

#pragma unroll
    for (int u = 0; u < 2; u++) {
        int mm = m0 + 32 * u;
        valid[u] = (mm < N_NEO);
        int mc = mm < N_NEO ? mm : (N_NEO - 1);
        cellc[u] = n * N_NEO + mc;

        // comms gather over 9 planes
        float av = sbias[1];
#pragma unroll
        for (int q = 0; q < 9; q++) {
            int i = q / 3, j = q % 3;
            av += hOld[q * G2 + (n + i) * G + (mc + j)];
        }
        a[u] = av;

        // perception: 3x3 img patch at perc position
        ushort2 p = g_perc[cellc[u]];
        pp[u] = p;
        float bv = sbias[0];
#pragma unroll
        for (int q = 0; q < 9; q++) {
            int i = q / 3, j = q % 3;
            bv = fmaf(img[(p.x + i) * G + (p.y + j)], spw[q], bv);
        }
        b[u] = bv;
    }

    float acc[2][9];
#pragma unroll
    for (int u = 0; u < 2; u++)
#pragma unroll
        for (int q = 0; q < 9; q++) acc[u][q] = 0.0f;

    // ---- hidden channels 0..63 ----
#pragma unroll 4
    for (int c4 = 0; c4 < 64; c4 += 4) {
        float4 u4 = *reinterpret_cast<const float4*>(&su[c4]);
        float4 v4 = *reinterpret_cast<const float4*>(&sv[c4]);
        float4 o4 = *reinterpret_cast<const float4*>(&sob[c4]);
        float s[2][4];
#pragma unroll
        for (int u = 0; u < 2; u++) {
            s[u][0] = sigmoid_pre(fmaf(a[u], u4.x, fmaf(b[u], v4.x, o4.x)));
            s[u][1] = sigmoid_pre(fmaf(a[u], u4.y, fmaf(b[u], v4.y, o4.y)));
            s[u][2] = sigmoid_pre(fmaf(a[u], u4.z, fmaf(b[u], v4.z, o4.z)));
            s[u][3] = sigmoid_pre(fmaf(a[u], u4.w, fmaf(b[u], v4.w, o4.w)));
        }
#pragma unroll
        for (int q = 0; q < 9; q++) {
            float4 w4 = *reinterpret_cast<const float4*>(&scw[q * 96 + c4]);
#pragma unroll
            for (int u = 0; u < 2; u++)
                acc[u][q] = fmaf(w4.x, s[u][0], fmaf(w4.y, s[u][1],
                            fmaf(w4.z, s[u][2], fmaf(w4.w, s[u][3], acc[u][q]))));
        }
    }

    // ---- class channels 64..95 (vectorized RMW into float4 scratch) ----
#pragma unroll 2
    for (int c4 = 64; c4 < 96; c4 += 4) {
        float4 u4 = *reinterpret_cast<const float4*>(&su[c4]);
        float4 v4 = *reinterpret_cast<const float4*>(&sv[c4]);
        float4 o4 = *reinterpret_cast<const float4*>(&sob[c4]);
        float s[2][4];
#pragma unroll
        for (int u = 0; u < 2; u++) {
            s[u][0] = sigmoid_pre(fmaf(a[u], u4.x, fmaf(b[u], v4.x, o4.x)));
            s[u][1] = sigmoid_pre(fmaf(a[u], u4.y, fmaf(b[u], v4.y, o4.y)));
            s[u][2] = sigmoid_pre(fmaf(a[u], u4.z, fmaf(b[u], v4.z, o4.z)));
            s[u][3] = sigmoid_pre(fmaf(a[u], u4.w, fmaf(b[u], v4.w, o4.w)));
        }
        int j4 = (c4 - 64) >> 2;
#pragma unroll
        for (int u = 0; u < 2; u++) {
            if (valid[u]) {
                float4 v = g_cls4[j4][cellc[u]];
                v.x += s[u][0]; v.y += s[u][1]; v.z += s[u][2]; v.w += s[u][3];
                g_cls4[j4][cellc[u]] = v;
            }
        }
#pragma unroll
        for (int q = 0; q < 9; q++) {
            float4 w4 = *reinterpret_cast<const float4*>(&scw[q * 96 + c4]);
#pragma unroll
            for (int u = 0; u < 2; u++)
                acc[u][q] = fmaf(w4.x, s[u][0], fmaf(w4.y, s[u][1],
                            fmaf(w4.z, s[u][2], fmaf(w4.w, s[u][3], acc[u][q]))));
        }
    }

    // ---- plane writes + action/perc update ----
    float u96 = su[96], v96 = sv[96], o96 = sob[96];
    float u97 = su[97], v97 = sv[97], o97 = sob[97];
#pragma unroll
    for (int u = 0; u < 2; u++) {
        if (!valid[u]) continue;
        int mm = m0 + 32 * u;
        int hc = (n + 1) * G + (mm + 1);
#pragma unroll
        for (int q = 0; q < 9; q++)
            hNew[q * G2 + hc] = hOld[q * G2 + hc] + acc[u][q];

        float s0 = sigmoid_pre(fmaf(a[u], u96, fmaf(b[u], v96, o96)));
        float s1 = sigmoid_pre(fmaf(a[u], u97, fmaf(b[u], v97, o97)));
        int dx = (s0 > NCA_THRESH) ? 1 : ((s0 < -NCA_THRESH) ? -1 : 0);
        int dy = (s1 > NCA_THRESH) ? 1 : ((s1 < -NCA_THRESH) ? -1 : 0);
        int px = min(max((int)pp[u].x + dx, 0), N_NEO - 1);
        int py = min(max((int)pp[u].y + dy, 0), N_NEO - 1);
        g_perc[cellc[u]] = make_ushort2((unsigned short)px, (unsigned short)py);
    }
}

extern "C" void kernel_launch(void* const* d_in, const int* in_sizes, int n_in,
                              void* d_out, int out_size) {
    const float* img     = (const float*)d_in[0];
    const float* comms_w = (const float*)d_in[1];
    const float* comms_b = (const float*)d_in[2];
    const float* perc_w  = (const float*)d_in[3];
    const float* perc_b  = (const float*)d_in[4];
    const float* out_w   = (const float*)d_in[5];
    const float* out_b   = (const float*)d_in[6];
    float* out = (float*)d_out;

    nca_init<<<1024, 256>>>();

    dim3 bs(32, 8);
    dim3 gs((N_NEO + 63) / 64, (N_NEO + 7) / 8);   // 8 x 64 = 512 blocks
    for (int t = 0; t < 50; t++)
        nca_step<<<gs, bs>>>(img, comms_w, comms_b, perc_w, perc_b,
                             out_w, out_b, t & 1);

    nca_final<<<(NCELLS + 255) / 256, 256>>>(out);
}

// round 12
// speedup vs baseline: 1.0421x; 1.0421x over previous
#include <cuda_runtime.h>

// MovingNCA, plane-reduced formulation:
//  state(96ch) -> 9 planes P_ij = <state, comms_w[i,j,:]>.
//  comms a = b_c + sum_ij P_ij(n+i,m+j); percep b = 3x3 img gather at perc pos.
//  s_c = sigmoid(a*u_c + b*v_c + ob_c); planes += W^T s; class ch -> scratch.
// R11: R9 config (2 cells/thread, 256-thr blocks, 512 blocks, 64 regs, the
//      measured plateau optimum) + the two cells packed into f32x2 lanes for
//      the 9-plane accumulation: 2 FFMA2 replace 4 FFMA per (q, ch-group).
//      acc2[9] = 18 regs = identical to scalar acc[2][9]. Weights duplicated
//      as (w,w) pairs in shared so they load as 64-bit fma2 operands.

#define N_NEO 510
#define G     512
#define G2    (G * G)
#define NCELLS (N_NEO * N_NEO)
#define NCA_THRESH 0.0007f
#define NLOG2E (-1.4426950408889634f)

__device__ float   g_h[2][9][G2];        // ping-pong comms planes
__device__ float4  g_cls4[8][NCELLS];    // class accumulators, 4 ch per float4
__device__ ushort2 g_perc[NCELLS];       // perception positions

__global__ void nca_init() {
    long stride = (long)gridDim.x * blockDim.x;
    long tid = (long)blockIdx.x * blockDim.x + threadIdx.x;
    float* h = &g_h[0][0][0];
    for (long i = tid; i < 2L * 9 * G2; i += stride) h[i] = 0.0f;
    float* c = &g_cls4[0][0].x;
    for (long i = tid; i < 32L * NCELLS; i += stride) c[i] = 0.0f;
    for (long i = tid; i < NCELLS; i += stride)
        g_perc[i] = make_ushort2((unsigned short)(i / N_NEO),
                                 (unsigned short)(i % N_NEO));
}

__global__ void nca_final(float* __restrict__ out) {
    int cell = blockIdx.x * 256 + threadIdx.x;
    if (cell >= NCELLS) return;
    float* op = out + (size_t)cell * 32;
#pragma unroll
    for (int j = 0; j < 8; j++)
        *reinterpret_cast<float4*>(op + 4 * j) = g_cls4[j][cell];
}

// weights prescaled by -log2(e): computes sigmoid(z) from x = -log2(e)*z
__device__ __forceinline__ float sigmoid_pre(float x) {
    float e;
    asm("ex2.approx.f32 %0, %1;" : "=f"(e) : "f"(x));
    float r;
    asm("rcp.approx.f32 %0, %1;" : "=f"(r) : "f"(1.0f + e));
    return r;
}

__device__ __forceinline__ unsigned long long pack2(float lo, float hi) {
    unsigned long long r;
    asm("mov.b64 %0, {%1, %2};" : "=l"(r) : "f"(lo), "f"(hi));
    return r;
}

__device__ __forceinline__ unsigned long long fma2(unsigned long long a,
                                                   unsigned long long b,
                                                   unsigned long long c) {
    unsigned long long d;
    asm("fma.rn.f32x2 %0, %1, %2, %3;" : "=l"(d) : "l"(a), "l"(b), "l"(c));
    return d;
}

__global__ __launch_bounds__(256, 4) void nca_step(
    const float* __restrict__ img,
    const float* __restrict__ comms_w,
    const float* __restrict__ comms_b,
    const float* __restrict__ perc_w,
    const float* __restrict__ perc_b,
    const float* __restrict__ out_w,
    const float* __restrict__ out_b,
    int parity)
{
    __shared__ __align__(16) float scw2[9 * 96 * 2];  // comms_w dup pairs [ij][c]{w,w}
    __shared__ __align__(16) float su[100], sv[100], sob[100];  // prescaled
    __shared__ float spw[9];
    __shared__ float sbias[2];                        // [0]=perc_b [1]=comms_b

    int t = threadIdx.y * 32 + threadIdx.x;
    for (int i = t; i < 864; i += 256) {
        float w = comms_w[i];
        scw2[2 * i]     = w;
        scw2[2 * i + 1] = w;
    }
    if (t < 98) {
        su[t]  = NLOG2E * out_w[t];
        sv[t]  = NLOG2E * out_w[98 + t];
        sob[t] = NLOG2E * out_b[t];
    }
    else if (t < 107) spw[t - 98] = perc_w[t - 98];
    else if (t == 107) sbias[0] = perc_b[0];
    else if (t == 108) sbias[1] = comms_b[0];
    __syncthreads();

    int n = blockIdx.y * 8 + threadIdx.y;
    if (n >= N_NEO) return;
    int m0 = blockIdx.x * 64 + threadIdx.x;

    const float* __restrict__ hOld = &g_h[parity][0][0];
    float* __restrict__ hNew = &g_h[parity ^ 1][0][0];

    bool valid[2];
    int  cellc[2];            // clamped cell index (safe reads)
    float a[2], b[2];
    ushort2 pp[2];

#pragma unroll
    for (int u = 0; u < 2; u++) {
        int mm = m0 + 32 * u;
        valid[u] = (mm < N_NEO);
        int mc = mm < N_NEO ? mm : (N_NEO - 1);
        cellc[u] = n * N_NEO + mc;

        // comms gather over 9 planes
        float av = sbias[1];
#pragma unroll
        for (int q = 0; q < 9; q++) {
            int i = q / 3, j = q % 3;
            av += hOld[q * G2 + (n + i) * G + (mc + j)];
        }
        a[u] = av;

        // perception: 3x3 img patch at perc position
        ushort2 p = g_perc[cellc[u]];
        pp[u] = p;
        float bv = sbias[0];
#pragma unroll
        for (int q = 0; q < 9; q++) {
            int i = q / 3, j = q % 3;
            bv = fmaf(img[(p.x + i) * G + (p.y + j)], spw[q], bv);
        }
        b[u] = bv;
    }

    // packed accumulators: lane lo = cell u0, lane hi = cell u1
    unsigned long long acc2[9];
#pragma unroll
    for (int q = 0; q < 9; q++) acc2[q] = 0ULL;

    // ---- hidden channels 0..63 ----
#pragma unroll 4
    for (int c4 = 0; c4 < 64; c4 += 4) {
        float4 u4 = *reinterpret_cast<const float4*>(&su[c4]);
        float4 v4 = *reinterpret_cast<const float4*>(&sv[c4]);
        float4 o4 = *reinterpret_cast<const float4*>(&sob[c4]);
        float s[2][4];
#pragma unroll
        for (int u = 0; u < 2; u++) {
            s[u][0] = sigmoid_pre(fmaf(a[u], u4.x, fmaf(b[u], v4.x, o4.x)));
            s[u][1] = sigmoid_pre(fmaf(a[u], u4.y, fmaf(b[u], v4.y, o4.y)));
            s[u][2] = sigmoid_pre(fmaf(a[u], u4.z, fmaf(b[u], v4.z, o4.z)));
            s[u][3] = sigmoid_pre(fmaf(a[u], u4.w, fmaf(b[u], v4.w, o4.w)));
        }
        unsigned long long s2[4];
#pragma unroll
        for (int k = 0; k < 4; k++) s2[k] = pack2(s[0][k], s[1][k]);
#pragma unroll
        for (int q = 0; q < 9; q++) {
            const ulonglong2* wp =
                reinterpret_cast<const ulonglong2*>(&scw2[(q * 96 + c4) * 2]);
            ulonglong2 wA = wp[0];   // channels c4, c4+1 (each duplicated)
            ulonglong2 wB = wp[1];   // channels c4+2, c4+3
            unsigned long long acc = acc2[q];
            acc = fma2(wA.x, s2[0], acc);
            acc = fma2(wA.y, s2[1], acc);
            acc = fma2(wB.x, s2[2], acc);
            acc = fma2(wB.y, s2[3], acc);
            acc2[q] = acc;
        }
    }

    // ---- class channels 64..95 (vectorized RMW into float4 scratch) ----
#pragma unroll 2
    for (int c4 = 64; c4 < 96; c4 += 4) {
        float4 u4 = *reinterpret_cast<const float4*>(&su[c4]);
        float4 v4 = *reinterpret_cast<const float4*>(&sv[c4]);
        float4 o4 = *reinterpret_cast<const float4*>(&sob[c4]);
        float s[2][4];
#pragma unroll
        for (int u = 0; u < 2; u++) {
            s[u][0] = sigmoid_pre(fmaf(a[u], u4.x, fmaf(b[u], v4.x, o4.x)));
            s[u][1] = sigmoid_pre(fmaf(a[u], u4.y, fmaf(b[u], v4.y, o4.y)));
            s[u][2] = sigmoid_pre(fmaf(a[u], u4.z, fmaf(b[u], v4.z, o4.z)));
            s[u][3] = sigmoid_pre(fmaf(a[u], u4.w, fmaf(b[u], v4.w, o4.w)));
        }
        int j4 = (c4 - 64) >> 2;
#pragma unroll
        for (int u = 0; u < 2; u++) {
            if (valid[u]) {
                float4 v = g_cls4[j4][cellc[u]];
                v.x += s[u][0]; v.y += s[u][1]; v.z += s[u][2]; v.w += s[u][3];
                g_cls4[j4][cellc[u]] = v;
            }
        }
        unsigned long long s2[4];
#pragma unroll
        for (int k = 0; k < 4; k++) s2[k] = pack2(s[0][k], s[1][k]);
#pragma unroll
        for (int q = 0; q < 9; q++) {
            const ulonglong2* wp =
                reinterpret_cast<const ulonglong2*>(&scw2[(q * 96 + c4) * 2]);
            ulonglong2 wA = wp[0];
            ulonglong2 wB = wp[1];
            unsigned long long acc = acc2[q];
            acc = fma2(wA.x, s2[0], acc);
            acc = fma2(wA.y, s2[1], acc);
            acc = fma2(wB.x, s2[2], acc);
            acc = fma2(wB.y, s2[3], acc);
            acc2[q] = acc;
        }
    }

    // ---- plane writes + action/perc update ----
    float u96 = su[96], v96 = sv[96], o96 = sob[96];
    float u97 = su[97], v97 = sv[97], o97 = sob[97];
#pragma unroll
    for (int u = 0; u < 2; u++) {
        if (!valid[u]) continue;
        int mm = m0 + 32 * u;
        int hc = (n + 1) * G + (mm + 1);
#pragma unroll
        for (int q = 0; q < 9; q++) {
            float lo, hi;
            asm("mov.b64 {%0, %1}, %2;" : "=f"(lo), "=f"(hi) : "l"(acc2[q]));
            float av = (u == 0) ? lo : hi;
            hNew[q * G2 + hc] = hOld[q * G2 + hc] + av;
        }

        float s0 = sigmoid_pre(fmaf(a[u], u96, fmaf(b[u], v96, o96)));
        float s1 = sigmoid_pre(fmaf(a[u], u97, fmaf(b[u], v97, o97)));
        int dx = (s0 > NCA_THRESH) ? 1 : ((s0 < -NCA_THRESH) ? -1 : 0);
        int dy = (s1 > NCA_THRESH) ? 1 : ((s1 < -NCA_THRESH) ? -1 : 0);
        int px = min(max((int)pp[u].x + dx, 0), N_NEO - 1);
        int py = min(max((int)pp[u].y + dy, 0), N_NEO - 1);
        g_perc[cellc[u]] = make_ushort2((unsigned short)px, (unsigned short)py);
    }
}

extern "C" void kernel_launch(void* const* d_in, const int* in_sizes, int n_in,
                              void* d_out, int out_size) {
    const float* img     = (const float*)d_in[0];
    const float* comms_w = (const float*)d_in[1];
    const float* comms_b = (const float*)d_in[2];
    const float* perc_w  = (const float*)d_in[3];
    const float* perc_b  = (const float*)d_in[4];
    const float* out_w   = (const float*)d_in[5];
    const float* out_b   = (const float*)d_in[6];
    float* out = (float*)d_out;

    nca_init<<<1024, 256>>>();

    dim3 bs(32, 8);
    dim3 gs((N_NEO + 63) / 64, (N_NEO + 7) / 8);   // 8 x 64 = 512 blocks
    for (int t = 0; t < 50; t++)
        nca_step<<<gs, bs>>>(img, comms_w, comms_b, perc_w, perc_b,
                             out_w, out_b, t & 1);

    nca_final<<<(NCELLS + 255) / 256, 256>>>(out);
}

// round 13
// speedup vs baseline: 1.1327x; 1.0869x over previous
#include <cuda_runtime.h>

// MovingNCA, plane-reduced formulation:
//  state(96ch) -> 9 planes P_ij = <state, comms_w[i,j,:]>.
//  comms a = b_c + sum_ij P_ij(n+i,m+j); percep b = 3x3 img gather at perc pos.
//  s_c = sigmoid(a*u_c + b*v_c + ob_c); planes += W^T s; class ch -> scratch.
// R13: R9 base (2 cells/thread, 256-thr blocks, 512 blocks, 64 regs) with the
//      class-scratch RMW replaced by red.global.add.v4.f32 (REDG): no read
//      traffic, no dependent-load stall, one producer per address per step so
//      results are bit-identical. Targets the ~46MB/step DRAM stream that the
//      R5-R12 plateau evidence attributes to the g_cls read-modify-write.

#define N_NEO 510
#define G     512
#define G2    (G * G)
#define NCELLS (N_NEO * N_NEO)
#define NCA_THRESH 0.0007f
#define NLOG2E (-1.4426950408889634f)

__device__ float   g_h[2][9][G2];        // ping-pong comms planes
__device__ float4  g_cls4[8][NCELLS];    // class accumulators, 4 ch per float4
__device__ ushort2 g_perc[NCELLS];       // perception positions

__global__ void nca_init() {
    long stride = (long)gridDim.x * blockDim.x;
    long tid = (long)blockIdx.x * blockDim.x + threadIdx.x;
    float* h = &g_h[0][0][0];
    for (long i = tid; i < 2L * 9 * G2; i += stride) h[i] = 0.0f;
    float* c = &g_cls4[0][0].x;
    for (long i = tid; i < 32L * NCELLS; i += stride) c[i] = 0.0f;
    for (long i = tid; i < NCELLS; i += stride)
        g_perc[i] = make_ushort2((unsigned short)(i / N_NEO),
                                 (unsigned short)(i % N_NEO));
}

__global__ void nca_final(float* __restrict__ out) {
    int cell = blockIdx.x * 256 + threadIdx.x;
    if (cell >= NCELLS) return;
    float* op = out + (size_t)cell * 32;
#pragma unroll
    for (int j = 0; j < 8; j++)
        *reinterpret_cast<float4*>(op + 4 * j) = g_cls4[j][cell];
}

// weights prescaled by -log2(e): computes sigmoid(z) from x = -log2(e)*z
__device__ __forceinline__ float sigmoid_pre(float x) {
    float e;
    asm("ex2.approx.f32 %0, %1;" : "=f"(e) : "f"(x));
    float r;
    asm("rcp.approx.f32 %0, %1;" : "=f"(r) : "f"(1.0f + e));
    return r;
}

__device__ __forceinline__ void red_add_v4(float* p, float s0, float s1,
                                           float s2, float s3) {
    asm volatile("red.global.add.v4.f32 [%0], {%1, %2, %3, %4};"
                 :: "l"(p), "f"(s0), "f"(s1), "f"(s2), "f"(s3) : "memory");
}

__global__ __launch_bounds__(256, 4) void nca_step(
    const float* __restrict__ img,
    const float* __restrict__ comms_w,
    const float* __restrict__ comms_b,
    const float* __restrict__ perc_w,
    const float* __restrict__ perc_b,
    const float* __restrict__ out_w,
    const float* __restrict__ out_b,
    int parity)
{
    __shared__ __align__(16) float scw[9 * 96];   // comms_w [ij][c]
    __shared__ __align__(16) float su[100], sv[100], sob[100];  // prescaled
    __shared__ float spw[9];
    __shared__ float sbias[2];                    // [0]=perc_b [1]=comms_b

    int t = threadIdx.y * 32 + threadIdx.x;
    for (int i = t; i < 864; i += 256) scw[i] = comms_w[i];
    if (t < 98) {
        su[t]  = NLOG2E * out_w[t];
        sv[t]  = NLOG2E * out_w[98 + t];
        sob[t] = NLOG2E * out_b[t];
    }
    else if (t < 107) spw[t - 98] = perc_w[t - 98];
    else if (t == 107) sbias[0] = perc_b[0];
    else if (t == 108) sbias[1] = comms_b[0];
    __syncthreads();

    int n = blockIdx.y * 8 + threadIdx.y;
    if (n >= N_NEO) return;
    int m0 = blockIdx.x * 64 + threadIdx.x;

    const float* __restrict__ hOld = &g_h[parity][0][0];
    float* __restrict__ hNew = &g_h[parity ^ 1][0][0];

    bool valid[2];
    int  cellc[2];            // clamped cell index (safe reads)
    float a[2], b[2];
    ushort2 pp[2];

#pragma unroll
    for (int u = 0; u < 2; u++) {
        int mm = m0 + 32 * u;
        valid[u] = (mm < N_NEO);
        int mc = mm < N_NEO ? mm : (N_NEO - 1);
        cellc[u] = n * N_NEO + mc;

        // comms gather over 9 planes
        float av = sbias[1];
#pragma unroll
        for (int q = 0; q < 9; q++) {
            int i = q / 3, j = q % 3;
            av += hOld[q * G2 + (n + i) * G + (mc + j)];
        }
        a[u] = av;

        // perception: 3x3 img patch at perc position
        ushort2 p = g_perc[cellc[u]];
        pp[u] = p;
        float bv = sbias[0];
#pragma unroll
        for (int q = 0; q < 9; q++) {
            int i = q / 3, j = q % 3;
            bv = fmaf(img[(p.x + i) * G + (p.y + j)], spw[q], bv);
        }
        b[u] = bv;
    }

    float acc[2][9];
#pragma unroll
    for (int u = 0; u < 2; u++)
#pragma unroll
        for (int q = 0; q < 9; q++) acc[u][q] = 0.0f;

    // ---- hidden channels 0..63 ----
#pragma unroll 4
    for (int c4 = 0; c4 < 64; c4 += 4) {
        float4 u4 = *reinterpret_cast<const float4*>(&su[c4]);
        float4 v4 = *reinterpret_cast<const float4*>(&sv[c4]);
        float4 o4 = *reinterpret_cast<const float4*>(&sob[c4]);
        float s[2][4];
#pragma unroll
        for (int u = 0; u < 2; u++) {
            s[u][0] = sigmoid_pre(fmaf(a[u], u4.x, fmaf(b[u], v4.x, o4.x)));
            s[u][1] = sigmoid_pre(fmaf(a[u], u4.y, fmaf(b[u], v4.y, o4.y)));
            s[u][2] = sigmoid_pre(fmaf(a[u], u4.z, fmaf(b[u], v4.z, o4.z)));
            s[u][3] = sigmoid_pre(fmaf(a[u], u4.w, fmaf(b[u], v4.w, o4.w)));
        }
#pragma unroll
        for (int q = 0; q < 9; q++) {
            float4 w4 = *reinterpret_cast<const float4*>(&scw[q * 96 + c4]);
#pragma unroll
            for (int u = 0; u < 2; u++)
                acc[u][q] = fmaf(w4.x, s[u][0], fmaf(w4.y, s[u][1],
                            fmaf(w4.z, s[u][2], fmaf(w4.w, s[u][3], acc[u][q]))));
        }
    }

    // ---- class channels 64..95 (REDG vector adds, no read) ----
#pragma unroll 2
    for (int c4 = 64; c4 < 96; c4 += 4) {
        float4 u4 = *reinterpret_cast<const float4*>(&su[c4]);
        float4 v4 = *reinterpret_cast<const float4*>(&sv[c4]);
        float4 o4 = *reinterpret_cast<const float4*>(&sob[c4]);
        float s[2][4];
#pragma unroll
        for (int u = 0; u < 2; u++) {
            s[u][0] = sigmoid_pre(fmaf(a[u], u4.x, fmaf(b[u], v4.x, o4.x)));
            s[u][1] = sigmoid_pre(fmaf(a[u], u4.y, fmaf(b[u], v4.y, o4.y)));
            s[u][2] = sigmoid_pre(fmaf(a[u], u4.z, fmaf(b[u], v4.z, o4.z)));
            s[u][3] = sigmoid_pre(fmaf(a[u], u4.w, fmaf(b[u], v4.w, o4.w)));
        }
        int j4 = (c4 - 64) >> 2;
#pragma unroll
        for (int u = 0; u < 2; u++) {
            if (valid[u])
                red_add_v4(&g_cls4[j4][cellc[u]].x,
                           s[u][0], s[u][1], s[u][2], s[u][3]);
        }
#pragma unroll
        for (int q = 0; q < 9; q++) {
            float4 w4 = *reinterpret_cast<const float4*>(&scw[q * 96 + c4]);
#pragma unroll
            for (int u = 0; u < 2; u++)
                acc[u][q] = fmaf(w4.x, s[u][0], fmaf(w4.y, s[u][1],
                            fmaf(w4.z, s[u][2], fmaf(w4.w, s[u][3], acc[u][q]))));
        }
    }

    // ---- plane writes + action/perc update ----
    float u96 = su[96], v96 = sv[96], o96 = sob[96];
    float u97 = su[97], v97 = sv[97], o97 = sob[97];
#pragma unroll
    for (int u = 0; u < 2; u++) {
        if (!valid[u]) continue;
        int mm = m0 + 32 * u;
        int hc = (n + 1) * G + (mm + 1);
#pragma unroll
        for (int q = 0; q < 9; q++)
            hNew[q * G2 + hc] = hOld[q * G2 + hc] + acc[u][q];

        float s0 = sigmoid_pre(fmaf(a[u], u96, fmaf(b[u], v96, o96)));
        float s1 = sigmoid_pre(fmaf(a[u], u97, fmaf(b[u], v97, o97)));
        int dx = (s0 > NCA_THRESH) ? 1 : ((s0 < -NCA_THRESH) ? -1 : 0);
        int dy = (s1 > NCA_THRESH) ? 1 : ((s1 < -NCA_THRESH) ? -1 : 0);
        int px = min(max((int)pp[u].x + dx, 0), N_NEO - 1);
        int py = min(max((int)pp[u].y + dy, 0), N_NEO - 1);
        g_perc[cellc[u]] = make_ushort2((unsigned short)px, (unsigned short)py);
    }
}

extern "C" void kernel_launch(void* const* d_in, const int* in_sizes, int n_in,
                              void* d_out, int out_size) {
    const float* img     = (const float*)d_in[0];
    const float* comms_w = (const float*)d_in[1];
    const float* comms_b = (const float*)d_in[2];
    const float* perc_w  = (const float*)d_in[3];
    const float* perc_b  = (const float*)d_in[4];
    const float* out_w   = (const float*)d_in[5];
    const float* out_b   = (const float*)d_in[6];
    float* out = (float*)d_out;

    nca_init<<<1024, 256>>>();

    dim3 bs(32, 8);
    dim3 gs((N_NEO + 63) / 64, (N_NEO + 7) / 8);   // 8 x 64 = 512 blocks
    for (int t = 0; t < 50; t++)
        nca_step<<<gs, bs>>>(img, comms_w, comms_b, perc_w, perc_b,
                             out_w, out_b, t & 1);

    nca_final<<<(NCELLS + 255) / 256, 256>>>(out);
}

// round 14
// speedup vs baseline: 1.2941x; 1.1425x over previous
#include <cuda_runtime.h>

// MovingNCA, plane-reduced formulation:
//  state(96ch) -> 9 planes P_ij = <state, comms_w[i,j,:]>.
//  comms a = b_c + sum_ij P_ij(n+i,m+j); percep b = 3x3 img gather at perc pos.
//  s_c = sigmoid(a*u_c + b*v_c + ob_c); planes += W^T s; class ch -> REDG scratch.
// R14: R13 base (2 cells/thread, 256-thr blocks, 512 blocks, REDG class
//      stores) + tanh path for the 64 hidden channels WITHOUT R8's confounds:
//        sigma(z) = 0.5 + 0.5 tanh(z/2);  w*sigma = (0.5w)*tanh + 0.5w
//      K_q = sum_c 0.5 w_qc precomputed ONCE in nca_init (g_K), half-weights
//      in shared. 1 MUFU per hidden sigmoid instead of 2 MUFU + 1 FADD.
//      Class + action channels keep the exact ex2+rcp path (R13 numerics).

#define N_NEO 510
#define G     512
#define G2    (G * G)
#define NCELLS (N_NEO * N_NEO)
#define NCA_THRESH 0.0007f
#define NLOG2E (-1.4426950408889634f)

__device__ float   g_h[2][9][G2];        // ping-pong comms planes
__device__ float4  g_cls4[8][NCELLS];    // class accumulators, 4 ch per float4
__device__ ushort2 g_perc[NCELLS];       // perception positions
__device__ float   g_K[9];               // K_q = sum_c 0.5*comms_w[q][c<64]

__global__ void nca_init(const float* __restrict__ comms_w) {
    long stride = (long)gridDim.x * blockDim.x;
    long tid = (long)blockIdx.x * blockDim.x + threadIdx.x;
    float* h = &g_h[0][0][0];
    for (long i = tid; i < 2L * 9 * G2; i += stride) h[i] = 0.0f;
    float* c = &g_cls4[0][0].x;
    for (long i = tid; i < 32L * NCELLS; i += stride) c[i] = 0.0f;
    for (long i = tid; i < NCELLS; i += stride)
        g_perc[i] = make_ushort2((unsigned short)(i / N_NEO),
                                 (unsigned short)(i % N_NEO));
    if (tid < 9) {
        float k = 0.0f;
        for (int cc = 0; cc < 64; cc++)
            k += 0.5f * comms_w[tid * 96 + cc];
        g_K[tid] = k;
    }
}

__global__ void nca_final(float* __restrict__ out) {
    int cell = blockIdx.x * 256 + threadIdx.x;
    if (cell >= NCELLS) return;
    float* op = out + (size_t)cell * 32;
#pragma unroll
    for (int j = 0; j < 8; j++)
        *reinterpret_cast<float4*>(op + 4 * j) = g_cls4[j][cell];
}

// exact sigmoid; weights prescaled by -log2(e): x = -log2(e)*z
__device__ __forceinline__ float sigmoid_pre(float x) {
    float e;
    asm("ex2.approx.f32 %0, %1;" : "=f"(e) : "f"(x));
    float r;
    asm("rcp.approx.f32 %0, %1;" : "=f"(r) : "f"(1.0f + e));
    return r;
}

__device__ __forceinline__ float tanh_apx(float x) {
    float r;
    asm("tanh.approx.f32 %0, %1;" : "=f"(r) : "f"(x));
    return r;
}

__device__ __forceinline__ void red_add_v4(float* p, float s0, float s1,
                                           float s2, float s3) {
    asm volatile("red.global.add.v4.f32 [%0], {%1, %2, %3, %4};"
                 :: "l"(p), "f"(s0), "f"(s1), "f"(s2), "f"(s3) : "memory");
}

__global__ __launch_bounds__(256, 4) void nca_step(
    const float* __restrict__ img,
    const float* __restrict__ comms_w,
    const float* __restrict__ comms_b,
    const float* __restrict__ perc_w,
    const float* __restrict__ perc_b,
    const float* __restrict__ out_w,
    const float* __restrict__ out_b,
    int parity)
{
    __shared__ __align__(16) float scwh[9 * 64];  // 0.5*comms_w, hidden ch
    __shared__ __align__(16) float scwc[9 * 32];  // comms_w, class ch
    __shared__ __align__(16) float su[100], sv[100], sob[100];  // prescaled
    __shared__ float spw[9], sK[9];
    __shared__ float sbias[2];                    // [0]=perc_b [1]=comms_b

    int t = threadIdx.y * 32 + threadIdx.x;
    for (int i = t; i < 864; i += 256) {
        int q = i / 96, c = i % 96;
        float w = comms_w[i];
        if (c < 64) scwh[q * 64 + c] = 0.5f * w;
        else        scwc[q * 32 + (c - 64)] = w;
    }
    if (t < 98) {
        float sc = (t < 64) ? 0.5f : NLOG2E;   // tanh half-arg vs ex2 prescale
        su[t]  = sc * out_w[t];
        sv[t]  = sc * out_w[98 + t];
        sob[t] = sc * out_b[t];
    }
    else if (t < 107) spw[t - 98] = perc_w[t - 98];
    else if (t == 107) sbias[0] = perc_b[0];
    else if (t == 108) sbias[1] = comms_b[0];
    else if (t >= 128 && t < 137) sK[t - 128] = g_K[t - 128];
    __syncthreads();

    int n = blockIdx.y * 8 + threadIdx.y;
    if (n >= N_NEO) return;
    int m0 = blockIdx.x * 64 + threadIdx.x;

    const float* __restrict__ hOld = &g_h[parity][0][0];
    float* __restrict__ hNew = &g_h[parity ^ 1][0][0];

    bool valid[2];
    int  cellc[2];            // clamped cell index (safe reads)
    float a[2], b[2];
    ushort2 pp[2];

#pragma unroll
    for (int u = 0; u < 2; u++) {
        int mm = m0 + 32 * u;
        valid[u] = (mm < N_NEO);
        int mc = mm < N_NEO ? mm : (N_NEO - 1);
        cellc[u] = n * N_NEO + mc;

        // comms gather over 9 planes
        float av = sbias[1];
#pragma unroll
        for (int q = 0; q < 9; q++) {
            int i = q / 3, j = q % 3;
            av += hOld[q * G2 + (n + i) * G + (mc + j)];
        }
        a[u] = av;

        // perception: 3x3 img patch at perc position
        ushort2 p = g_perc[cellc[u]];
        pp[u] = p;
        float bv = sbias[0];
#pragma unroll
        for (int q = 0; q < 9; q++) {
            int i = q / 3, j = q % 3;
            bv = fmaf(img[(p.x + i) * G + (p.y + j)], spw[q], bv);
        }
        b[u] = bv;
    }

    float acc[2][9];
#pragma unroll
    for (int u = 0; u < 2; u++)
#pragma unroll
        for (int q = 0; q < 9; q++) acc[u][q] = sK[q];

    // ---- hidden channels 0..63 : tanh path, folded affine ----
#pragma unroll 4
    for (int c4 = 0; c4 < 64; c4 += 4) {
        float4 u4 = *reinterpret_cast<const float4*>(&su[c4]);
        float4 v4 = *reinterpret_cast<const float4*>(&sv[c4]);
        float4 o4 = *reinterpret_cast<const float4*>(&sob[c4]);
        float s[2][4];
#pragma unroll
        for (int u = 0; u < 2; u++) {
            s[u][0] = tanh_apx(fmaf(a[u], u4.x, fmaf(b[u], v4.x, o4.x)));
            s[u][1] = tanh_apx(fmaf(a[u], u4.y, fmaf(b[u], v4.y, o4.y)));
            s[u][2] = tanh_apx(fmaf(a[u], u4.z, fmaf(b[u], v4.z, o4.z)));
            s[u][3] = tanh_apx(fmaf(a[u], u4.w, fmaf(b[u], v4.w, o4.w)));
        }
#pragma unroll
        for (int q = 0; q < 9; q++) {
            float4 w4 = *reinterpret_cast<const float4*>(&scwh[q * 64 + c4]);
#pragma unroll
            for (int u = 0; u < 2; u++)
                acc[u][q] = fmaf(w4.x, s[u][0], fmaf(w4.y, s[u][1],
                            fmaf(w4.z, s[u][2], fmaf(w4.w, s[u][3], acc[u][q]))));
        }
    }

    // ---- class channels 64..95 : exact path, REDG vector adds ----
#pragma unroll 2
    for (int k4 = 0; k4 < 32; k4 += 4) {
        float4 u4 = *reinterpret_cast<const float4*>(&su[64 + k4]);
        float4 v4 = *reinterpret_cast<const float4*>(&sv[64 + k4]);
        float4 o4 = *reinterpret_cast<const float4*>(&sob[64 + k4]);
        float s[2][4];
#pragma unroll
        for (int u = 0; u < 2; u++) {
            s[u][0] = sigmoid_pre(fmaf(a[u], u4.x, fmaf(b[u], v4.x, o4.x)));
            s[u][1] = sigmoid_pre(fmaf(a[u], u4.y, fmaf(b[u], v4.y, o4.y)));
            s[u][2] = sigmoid_pre(fmaf(a[u], u4.z, fmaf(b[u], v4.z, o4.z)));
            s[u][3] = sigmoid_pre(fmaf(a[u], u4.w, fmaf(b[u], v4.w, o4.w)));
        }
        int j4 = k4 >> 2;
#pragma unroll
        for (int u = 0; u < 2; u++) {
            if (valid[u])
                red_add_v4(&g_cls4[j4][cellc[u]].x,
                           s[u][0], s[u][1], s[u][2], s[u][3]);
        }
#pragma unroll
        for (int q = 0; q < 9; q++) {
            float4 w4 = *reinterpret_cast<const float4*>(&scwc[q * 32 + k4]);
#pragma unroll
            for (int u = 0; u < 2; u++)
                acc[u][q] = fmaf(w4.x, s[u][0], fmaf(w4.y, s[u][1],
                            fmaf(w4.z, s[u][2], fmaf(w4.w, s[u][3], acc[u][q]))));
        }
    }

    // ---- plane writes + action/perc update (exact path) ----
    float u96 = su[96], v96 = sv[96], o96 = sob[96];
    float u97 = su[97], v97 = sv[97], o97 = sob[97];
#pragma unroll
    for (int u = 0; u < 2; u++) {
        if (!valid[u]) continue;
        int mm = m0 + 32 * u;
        int hc = (n + 1) * G + (mm + 1);
#pragma unroll
        for (int q = 0; q < 9; q++)
            hNew[q * G2 + hc] = hOld[q * G2 + hc] + acc[u][q];

        float s0 = sigmoid_pre(fmaf(a[u], u96, fmaf(b[u], v96, o96)));
        float s1 = sigmoid_pre(fmaf(a[u], u97, fmaf(b[u], v97, o97)));
        int dx = (s0 > NCA_THRESH) ? 1 : ((s0 < -NCA_THRESH) ? -1 : 0);
        int dy = (s1 > NCA_THRESH) ? 1 : ((s1 < -NCA_THRESH) ? -1 : 0);
        int px = min(max((int)pp[u].x + dx, 0), N_NEO - 1);
        int py = min(max((int)pp[u].y + dy, 0), N_NEO - 1);
        g_perc[cellc[u]] = make_ushort2((unsigned short)px, (unsigned short)py);
    }
}

extern "C" void kernel_launch(void* const* d_in, const int* in_sizes, int n_in,
                              void* d_out, int out_size) {
    const float* img     = (const float*)d_in[0];
    const float* comms_w = (const float*)d_in[1];
    const float* comms_b = (const float*)d_in[2];
    const float* perc_w  = (const float*)d_in[3];
    const float* perc_b  = (const float*)d_in[4];
    const float* out_w   = (const float*)d_in[5];
    const float* out_b   = (const float*)d_in[6];
    float* out = (float*)d_out;

    nca_init<<<1024, 256>>>(comms_w);

    dim3 bs(32, 8);
    dim3 gs((N_NEO + 63) / 64, (N_NEO + 7) / 8);   // 8 x 64 = 512 blocks
    for (int t = 0; t < 50; t++)
        nca_step<<<gs, bs>>>(img, comms_w, comms_b, perc_w, perc_b,
                             out_w, out_b, t & 1);

    nca_final<<<(NCELLS + 255) / 256, 256>>>(out);
}

// round 15
// speedup vs baseline: 1.3865x; 1.0714x over previous
#include <cuda_runtime.h>

// MovingNCA, plane-reduced formulation:
//  state(96ch) -> 9 planes P_ij = <state, comms_w[i,j,:]>.
//  comms a = b_c + sum_ij P_ij(n+i,m+j); percep b = 3x3 img gather at perc pos.
//  s_c = sigmoid(a*u_c + b*v_c + ob_c); planes += W^T s; class ch -> REDG scratch.
// R15: R14 + tanh folding extended to ALL 96 state channels:
//        sigma(z) = 0.5 + 0.5 tanh(z/2);  w*sigma = (0.5w)*tanh + 0.5w
//      K_q = sum_{c<96} 0.5 w_qc (precomputed in nca_init). Class REDG values
//      need one extra FMA: s = 0.5 + 0.5 t. Removes 32 ex2 + 32 rcp + 32 fadd
//      per cell (MUFU ops 132 -> 100). Action channels (96,97) keep the exact
//      ex2+rcp path so perc threshold decisions stay bit-stable.

#define N_NEO 510
#define G     512
#define G2    (G * G)
#define NCELLS (N_NEO * N_NEO)
#define NCA_THRESH 0.0007f
#define NLOG2E (-1.4426950408889634f)

__device__ float   g_h[2][9][G2];        // ping-pong comms planes
__device__ float4  g_cls4[8][NCELLS];    // class accumulators, 4 ch per float4
__device__ ushort2 g_perc[NCELLS];       // perception positions
__device__ float   g_K[9];               // K_q = sum_{c<96} 0.5*comms_w[q][c]

__global__ void nca_init(const float* __restrict__ comms_w) {
    long stride = (long)gridDim.x * blockDim.x;
    long tid = (long)blockIdx.x * blockDim.x + threadIdx.x;
    float* h = &g_h[0][0][0];
    for (long i = tid; i < 2L * 9 * G2; i += stride) h[i] = 0.0f;
    float* c = &g_cls4[0][0].x;
    for (long i = tid; i < 32L * NCELLS; i += stride) c[i] = 0.0f;
    for (long i = tid; i < NCELLS; i += stride)
        g_perc[i] = make_ushort2((unsigned short)(i / N_NEO),
                                 (unsigned short)(i % N_NEO));
    if (tid < 9) {
        float k = 0.0f;
        for (int cc = 0; cc < 96; cc++)
            k += 0.5f * comms_w[tid * 96 + cc];
        g_K[tid] = k;
    }
}

__global__ void nca_final(float* __restrict__ out) {
    int cell = blockIdx.x * 256 + threadIdx.x;
    if (cell >= NCELLS) return;
    float* op = out + (size_t)cell * 32;
#pragma unroll
    for (int j = 0; j < 8; j++)
        *reinterpret_cast<float4*>(op + 4 * j) = g_cls4[j][cell];
}

// exact sigmoid; weights prescaled by -log2(e): x = -log2(e)*z
__device__ __forceinline__ float sigmoid_pre(float x) {
    float e;
    asm("ex2.approx.f32 %0, %1;" : "=f"(e) : "f"(x));
    float r;
    asm("rcp.approx.f32 %0, %1;" : "=f"(r) : "f"(1.0f + e));
    return r;
}

__device__ __forceinline__ float tanh_apx(float x) {
    float r;
    asm("tanh.approx.f32 %0, %1;" : "=f"(r) : "f"(x));
    return r;
}

__device__ __forceinline__ void red_add_v4(float* p, float s0, float s1,
                                           float s2, float s3) {
    asm volatile("red.global.add.v4.f32 [%0], {%1, %2, %3, %4};"
                 :: "l"(p), "f"(s0), "f"(s1), "f"(s2), "f"(s3) : "memory");
}

__global__ __launch_bounds__(256, 4) void nca_step(
    const float* __restrict__ img,
    const float* __restrict__ comms_w,
    const float* __restrict__ comms_b,
    const float* __restrict__ perc_w,
    const float* __restrict__ perc_b,
    const float* __restrict__ out_w,
    const float* __restrict__ out_b,
    int parity)
{
    __shared__ __align__(16) float scw[9 * 96];   // 0.5*comms_w, all channels
    __shared__ __align__(16) float su[100], sv[100], sob[100];  // prescaled
    __shared__ float spw[9], sK[9];
    __shared__ float sbias[2];                    // [0]=perc_b [1]=comms_b

    int t = threadIdx.y * 32 + threadIdx.x;
    for (int i = t; i < 864; i += 256) scw[i] = 0.5f * comms_w[i];
    if (t < 98) {
        float sc = (t < 96) ? 0.5f : NLOG2E;   // tanh half-arg vs ex2 prescale
        su[t]  = sc * out_w[t];
        sv[t]  = sc * out_w[98 + t];
        sob[t] = sc * out_b[t];
    }
    else if (t < 107) spw[t - 98] = perc_w[t - 98];
    else if (t == 107) sbias[0] = perc_b[0];
    else if (t == 108) sbias[1] = comms_b[0];
    else if (t >= 128 && t < 137) sK[t - 128] = g_K[t - 128];
    __syncthreads();

    int n = blockIdx.y * 8 + threadIdx.y;
    if (n >= N_NEO) return;
    int m0 = blockIdx.x * 64 + threadIdx.x;

    const float* __restrict__ hOld = &g_h[parity][0][0];
    float* __restrict__ hNew = &g_h[parity ^ 1][0][0];

    bool valid[2];
    int  cellc[2];            // clamped cell index (safe reads)
    float a[2], b[2];
    ushort2 pp[2];

#pragma unroll
    for (int u = 0; u < 2; u++) {
        int mm = m0 + 32 * u;
        valid[u] = (mm < N_NEO);
        int mc = mm < N_NEO ? mm : (N_NEO - 1);
        cellc[u] = n * N_NEO + mc;

        // comms gather over 9 planes
        float av = sbias[1];
#pragma unroll
        for (int q = 0; q < 9; q++) {
            int i = q / 3, j = q % 3;
            av += hOld[q * G2 + (n + i) * G + (mc + j)];
        }
        a[u] = av;

        // perception: 3x3 img patch at perc position
        ushort2 p = g_perc[cellc[u]];
        pp[u] = p;
        float bv = sbias[0];
#pragma unroll
        for (int q = 0; q < 9; q++) {
            int i = q / 3, j = q % 3;
            bv = fmaf(img[(p.x + i) * G + (p.y + j)], spw[q], bv);
        }
        b[u] = bv;
    }

    float acc[2][9];
#pragma unroll
    for (int u = 0; u < 2; u++)
#pragma unroll
        for (int q = 0; q < 9; q++) acc[u][q] = sK[q];

    // ---- hidden channels 0..63 : tanh path, folded affine ----
#pragma unroll 4
    for (int c4 = 0; c4 < 64; c4 += 4) {
        float4 u4 = *reinterpret_cast<const float4*>(&su[c4]);
        float4 v4 = *reinterpret_cast<const float4*>(&sv[c4]);
        float4 o4 = *reinterpret_cast<const float4*>(&sob[c4]);
        float s[2][4];
#pragma unroll
        for (int u = 0; u < 2; u++) {
            s[u][0] = tanh_apx(fmaf(a[u], u4.x, fmaf(b[u], v4.x, o4.x)));
            s[u][1] = tanh_apx(fmaf(a[u], u4.y, fmaf(b[u], v4.y, o4.y)));
            s[u][2] = tanh_apx(fmaf(a[u], u4.z, fmaf(b[u], v4.z, o4.z)));
            s[u][3] = tanh_apx(fmaf(a[u], u4.w, fmaf(b[u], v4.w, o4.w)));
        }
#pragma unroll
        for (int q = 0; q < 9; q++) {
            float4 w4 = *reinterpret_cast<const float4*>(&scw[q * 96 + c4]);
#pragma unroll
            for (int u = 0; u < 2; u++)
                acc[u][q] = fmaf(w4.x, s[u][0], fmaf(w4.y, s[u][1],
                            fmaf(w4.z, s[u][2], fmaf(w4.w, s[u][3], acc[u][q]))));
        }
    }

    // ---- class channels 64..95 : tanh path + REDG (s = 0.5 + 0.5 t) ----
#pragma unroll 2
    for (int c4 = 64; c4 < 96; c4 += 4) {
        float4 u4 = *reinterpret_cast<const float4*>(&su[c4]);
        float4 v4 = *reinterpret_cast<const float4*>(&sv[c4]);
        float4 o4 = *reinterpret_cast<const float4*>(&sob[c4]);
        float s[2][4];
#pragma unroll
        for (int u = 0; u < 2; u++) {
            s[u][0] = tanh_apx(fmaf(a[u], u4.x, fmaf(b[u], v4.x, o4.x)));
            s[u][1] = tanh_apx(fmaf(a[u], u4.y, fmaf(b[u], v4.y, o4.y)));
            s[u][2] = tanh_apx(fmaf(a[u], u4.z, fmaf(b[u], v4.z, o4.z)));
            s[u][3] = tanh_apx(fmaf(a[u], u4.w, fmaf(b[u], v4.w, o4.w)));
        }
        int j4 = (c4 - 64) >> 2;
#pragma unroll
        for (int u = 0; u < 2; u++) {
            if (valid[u])
                red_add_v4(&g_cls4[j4][cellc[u]].x,
                           fmaf(0.5f, s[u][0], 0.5f),
                           fmaf(0.5f, s[u][1], 0.5f),
                           fmaf(0.5f, s[u][2], 0.5f),
                           fmaf(0.5f, s[u][3], 0.5f));
        }
#pragma unroll
        for (int q = 0; q < 9; q++) {
            float4 w4 = *reinterpret_cast<const float4*>(&scw[q * 96 + c4]);
#pragma unroll
            for (int u = 0; u < 2; u++)
                acc[u][q] = fmaf(w4.x, s[u][0], fmaf(w4.y, s[u][1],
                            fmaf(w4.z, s[u][2], fmaf(w4.w, s[u][3], acc[u][q]))));
        }
    }

    // ---- plane writes + action/perc update (exact path) ----
    float u96 = su[96], v96 = sv[96], o96 = sob[96];
    float u97 = su[97], v97 = sv[97], o97 = sob[97];
#pragma unroll
    for (int u = 0; u < 2; u++) {
        if (!valid[u]) continue;
        int mm = m0 + 32 * u;
        int hc = (n + 1) * G + (mm + 1);
#pragma unroll
        for (int q = 0; q < 9; q++)
            hNew[q * G2 + hc] = hOld[q * G2 + hc] + acc[u][q];

        float s0 = sigmoid_pre(fmaf(a[u], u96, fmaf(b[u], v96, o96)));
        float s1 = sigmoid_pre(fmaf(a[u], u97, fmaf(b[u], v97, o97)));
        int dx = (s0 > NCA_THRESH) ? 1 : ((s0 < -NCA_THRESH) ? -1 : 0);
        int dy = (s1 > NCA_THRESH) ? 1 : ((s1 < -NCA_THRESH) ? -1 : 0);
        int px = min(max((int)pp[u].x + dx, 0), N_NEO - 1);
        int py = min(max((int)pp[u].y + dy, 0), N_NEO - 1);
        g_perc[cellc[u]] = make_ushort2((unsigned short)px, (unsigned short)py);
    }
}

extern "C" void kernel_launch(void* const* d_in, const int* in_sizes, int n_in,
                              void* d_out, int out_size) {
    const float* img     = (const float*)d_in[0];
    const float* comms_w = (const float*)d_in[1];
    const float* comms_b = (const float*)d_in[2];
    const float* perc_w  = (const float*)d_in[3];
    const float* perc_b  = (const float*)d_in[4];
    const float* out_w   = (const float*)d_in[5];
    const float* out_b   = (const float*)d_in[6];
    float* out = (float*)d_out;

    nca_init<<<1024, 256>>>(comms_w);

    dim3 bs(32, 8);
    dim3 gs((N_NEO + 63) / 64, (N_NEO + 7) / 8);   // 8 x 64 = 512 blocks
    for (int t = 0; t < 50; t++)
        nca_step<<<gs, bs>>>(img, comms_w, comms_b, perc_w, perc_b,
                             out_w, out_b, t & 1);

    nca_final<<<(NCELLS + 255) / 256, 256>>>(out);
}